// round 3
// baseline (speedup 1.0000x reference)
#include <cuda_runtime.h>
#include <cstdint>

// Masked row-wise cumsum: out[r,:] = cumsum(x[r,:] * mask[r,:])
// x: f32 [4096, 32768]; mask: bool on the wire (detected: 4-byte 0/1 words,
// but byte fallback kept); out: f32 [4096, 32768].
//
// One CTA per row. 512 threads x 8 elems = 4096-elem chunks, 8 chunks/row.
// Software-pipelined loads (next chunk's raw x+mask issued before current
// chunk's scan), single __syncthreads per chunk via ping-pong warp totals +
// redundant per-warp scan of the 16 warp totals.

#ifndef CUMSUM_N
#define CUMSUM_N 32768
#endif

#define TPB   512
#define VEC   8
#define CHUNK (TPB * VEC)   // 4096
#define NWARP (TPB / 32)    // 16

__global__ __launch_bounds__(TPB, 2)
void masked_cumsum_row_kernel(const float* __restrict__ x,
                              const void* __restrict__ mask,
                              float* __restrict__ out,
                              int n_cols)
{
    const int row   = blockIdx.x;
    const size_t base = (size_t)row * (size_t)n_cols;

    const int tid  = threadIdx.x;
    const int lane = tid & 31;
    const int wid  = tid >> 5;

    // --- per-warp mask dtype detection (deterministic, no barrier) ---
    // Sample the first 32 words of the mask buffer (in-bounds under every
    // candidate encoding). A 4-byte 0/1 encoding only produces 0, 1 (int) or
    // 0x3F800000 (float 1.0); random 0/1 BYTES make other words w.p. 7/8 each.
    {
    }
    const unsigned probe = ((const unsigned*)mask)[lane];
    const bool clean = (probe == 0u) | (probe == 1u) | (probe == 0x3F800000u);
    const bool word_mode = __all_sync(0xffffffffu, clean);

    __shared__ float s_warp[2][NWARP];

    float carry = 0.0f;
    const int nch = n_cols / CHUNK;

    // ---- prefetch chunk 0 ----
    size_t off = base + (size_t)tid * VEC;
    float4 xa = *reinterpret_cast<const float4*>(x + off);
    float4 xb = *reinterpret_cast<const float4*>(x + off + 4);
    uint4  ma, mb;           // word-mode raw mask
    uint2  mby;              // byte-mode raw mask (8 bytes)
    if (word_mode) {
        ma = *reinterpret_cast<const uint4*>((const unsigned*)mask + off);
        mb = *reinterpret_cast<const uint4*>((const unsigned*)mask + off + 4);
    } else {
        mby = *reinterpret_cast<const uint2*>((const uint8_t*)mask + off);
    }

    int p = 0;
    for (int c = 0; c < nch; c++) {
        // ---- issue next chunk's loads before any compute/barrier ----
        float4 nxa, nxb;
        uint4  nma, nmb;
        uint2  nmby;
        const size_t noff = off + CHUNK;
        if (c + 1 < nch) {
            nxa = *reinterpret_cast<const float4*>(x + noff);
            nxb = *reinterpret_cast<const float4*>(x + noff + 4);
            if (word_mode) {
                nma = *reinterpret_cast<const uint4*>((const unsigned*)mask + noff);
                nmb = *reinterpret_cast<const uint4*>((const unsigned*)mask + noff + 4);
            } else {
                nmby = *reinterpret_cast<const uint2*>((const uint8_t*)mask + noff);
            }
        } else {
            nxa = make_float4(0.f, 0.f, 0.f, 0.f);
            nxb = make_float4(0.f, 0.f, 0.f, 0.f);
            nma = make_uint4(0u, 0u, 0u, 0u);
            nmb = make_uint4(0u, 0u, 0u, 0u);
            nmby = make_uint2(0u, 0u);
        }

        // ---- apply mask ----
        float v0, v1, v2, v3, v4, v5, v6, v7;
        if (word_mode) {
            v0 = ma.x ? xa.x : 0.f;  v1 = ma.y ? xa.y : 0.f;
            v2 = ma.z ? xa.z : 0.f;  v3 = ma.w ? xa.w : 0.f;
            v4 = mb.x ? xb.x : 0.f;  v5 = mb.y ? xb.y : 0.f;
            v6 = mb.z ? xb.z : 0.f;  v7 = mb.w ? xb.w : 0.f;
        } else {
            v0 = (mby.x & 0x000000FFu) ? xa.x : 0.f;
            v1 = (mby.x & 0x0000FF00u) ? xa.y : 0.f;
            v2 = (mby.x & 0x00FF0000u) ? xa.z : 0.f;
            v3 = (mby.x & 0xFF000000u) ? xa.w : 0.f;
            v4 = (mby.y & 0x000000FFu) ? xb.x : 0.f;
            v5 = (mby.y & 0x0000FF00u) ? xb.y : 0.f;
            v6 = (mby.y & 0x00FF0000u) ? xb.z : 0.f;
            v7 = (mby.y & 0xFF000000u) ? xb.w : 0.f;
        }

        // ---- thread-local inclusive scan of 8 ----
        float s0 = v0;
        float s1 = s0 + v1;
        float s2 = s1 + v2;
        float s3 = s2 + v3;
        float s4 = s3 + v4;
        float s5 = s4 + v5;
        float s6 = s5 + v6;
        float s7 = s6 + v7;

        // ---- warp inclusive scan of per-thread totals ----
        float t = s7;
        #pragma unroll
        for (int d = 1; d < 32; d <<= 1) {
            float nv = __shfl_up_sync(0xffffffffu, t, d);
            if (lane >= d) t += nv;
        }
        const float thread_excl = t - s7;

        if (lane == 31) s_warp[p][wid] = t;
        __syncthreads();   // the ONLY barrier per chunk

        // ---- every warp redundantly scans the 16 warp totals ----
        float wt = (lane < NWARP) ? s_warp[p][lane] : 0.f;
        float wincl = wt;
        #pragma unroll
        for (int d = 1; d < NWARP; d <<= 1) {
            float nv = __shfl_up_sync(0xffffffffu, wincl, d);
            if (lane >= d) wincl += nv;
        }
        const float warp_excl = (wid == 0)
            ? 0.f
            : __shfl_sync(0xffffffffu, wincl, wid - 1);
        const float block_tot = __shfl_sync(0xffffffffu, wincl, NWARP - 1);

        const float offv = carry + warp_excl + thread_excl;

        float4 oa, ob;
        oa.x = s0 + offv;  oa.y = s1 + offv;
        oa.z = s2 + offv;  oa.w = s3 + offv;
        ob.x = s4 + offv;  ob.y = s5 + offv;
        ob.z = s6 + offv;  ob.w = s7 + offv;
        *reinterpret_cast<float4*>(out + off)     = oa;
        *reinterpret_cast<float4*>(out + off + 4) = ob;

        carry += block_tot;

        // ---- rotate pipeline ----
        xa = nxa; xb = nxb; ma = nma; mb = nmb; mby = nmby;
        off = noff;
        p ^= 1;
    }
}

extern "C" void kernel_launch(void* const* d_in, const int* in_sizes, int n_in,
                              void* d_out, int out_size)
{
    const float* x    = (const float*)d_in[0];
    const void*  mask = d_in[1];
    float*       out  = (float*)d_out;

    const int n_cols = CUMSUM_N;
    const int n_rows = in_sizes[0] / n_cols;   // 4096

    masked_cumsum_row_kernel<<<n_rows, TPB>>>(x, mask, out, n_cols);
}

// round 4
// speedup vs baseline: 1.0199x; 1.0199x over previous
#include <cuda_runtime.h>
#include <cstdint>

// Masked row-wise cumsum: out[r,:] = cumsum(x[r,:] * mask[r,:])
// x: f32 [4096, 32768]; mask: bool on the wire (observed: 4-byte 0/1 words;
// byte fallback kept); out: f32 [4096, 32768].
//
// One CTA per row, 1024 threads x 4 elems = 4096-elem chunks, 8 chunks/row.
// ONE __syncthreads per chunk: ping-pong warp-totals buffer + every warp
// redundantly shfl-scans the 32 warp totals (no warp-0 bottleneck, no
// trailing WAR barrier). launch_bounds(1024,2) pins regs <= 32 so both CTAs
// stay resident (R3 lesson: occupancy >> explicit prefetch here).

#ifndef CUMSUM_N
#define CUMSUM_N 32768
#endif

#define TPB   1024
#define VEC   4
#define CHUNK (TPB * VEC)   // 4096
#define NWARP (TPB / 32)    // 32  (exactly one warp-width scan)

__global__ __launch_bounds__(TPB, 2)
void masked_cumsum_row_kernel(const float* __restrict__ x,
                              const void* __restrict__ mask,
                              float* __restrict__ out,
                              int n_cols)
{
    const int row   = blockIdx.x;
    const size_t base = (size_t)row * (size_t)n_cols;

    const int tid  = threadIdx.x;
    const int lane = tid & 31;
    const int wid  = tid >> 5;

    // --- per-warp mask dtype detection (deterministic, no barrier) ---
    // First 32 words of mask buffer: a 4-byte 0/1 encoding only yields
    // 0, 1 (int32) or 0x3F800000 (f32 1.0); random 0/1 BYTES almost surely
    // produce other words (p = 7/8 per word, 32 samples).
    const unsigned probe = ((const unsigned*)mask)[lane];
    const bool clean = (probe == 0u) | (probe == 1u) | (probe == 0x3F800000u);
    const bool word_mode = __all_sync(0xffffffffu, clean);

    __shared__ float s_warp[2][NWARP];

    float carry = 0.0f;
    int p = 0;

    #pragma unroll 1
    for (int c = 0; c < n_cols; c += CHUNK) {
        const size_t off = base + (size_t)c + (size_t)tid * VEC;

        const float4 xv = *reinterpret_cast<const float4*>(x + off);

        float v0, v1, v2, v3;
        if (word_mode) {
            const uint4 mv = *reinterpret_cast<const uint4*>((const unsigned*)mask + off);
            v0 = mv.x ? xv.x : 0.f;
            v1 = mv.y ? xv.y : 0.f;
            v2 = mv.z ? xv.z : 0.f;
            v3 = mv.w ? xv.w : 0.f;
        } else {
            const unsigned mv = *reinterpret_cast<const unsigned*>((const uint8_t*)mask + off);
            v0 = (mv & 0x000000FFu) ? xv.x : 0.f;
            v1 = (mv & 0x0000FF00u) ? xv.y : 0.f;
            v2 = (mv & 0x00FF0000u) ? xv.z : 0.f;
            v3 = (mv & 0xFF000000u) ? xv.w : 0.f;
        }

        // thread-local inclusive scan of 4
        const float s0 = v0;
        const float s1 = s0 + v1;
        const float s2 = s1 + v2;
        const float s3 = s2 + v3;

        // warp inclusive scan of per-thread totals
        float t = s3;
        #pragma unroll
        for (int d = 1; d < 32; d <<= 1) {
            float nv = __shfl_up_sync(0xffffffffu, t, d);
            if (lane >= d) t += nv;
        }
        const float thread_excl = t - s3;

        if (lane == 31) s_warp[p][wid] = t;
        __syncthreads();                       // the ONLY barrier per chunk

        // every warp redundantly scans the 32 warp totals
        float wincl = s_warp[p][lane];
        #pragma unroll
        for (int d = 1; d < NWARP; d <<= 1) {
            float nv = __shfl_up_sync(0xffffffffu, wincl, d);
            if (lane >= d) wincl += nv;
        }
        const float warp_excl = (wid == 0)
            ? 0.f
            : __shfl_sync(0xffffffffu, wincl, wid - 1);
        const float block_tot = __shfl_sync(0xffffffffu, wincl, NWARP - 1);

        const float offv = carry + warp_excl + thread_excl;

        float4 o;
        o.x = s0 + offv;
        o.y = s1 + offv;
        o.z = s2 + offv;
        o.w = s3 + offv;
        *reinterpret_cast<float4*>(out + off) = o;

        carry += block_tot;
        p ^= 1;    // next chunk writes the other buffer -> no trailing barrier
    }
}

extern "C" void kernel_launch(void* const* d_in, const int* in_sizes, int n_in,
                              void* d_out, int out_size)
{
    const float* x    = (const float*)d_in[0];
    const void*  mask = d_in[1];
    float*       out  = (float*)d_out;

    const int n_cols = CUMSUM_N;
    const int n_rows = in_sizes[0] / n_cols;   // 4096

    masked_cumsum_row_kernel<<<n_rows, TPB>>>(x, mask, out, n_cols);
}

// round 5
// speedup vs baseline: 1.0813x; 1.0603x over previous
#include <cuda_runtime.h>
#include <cstdint>

// Masked row-wise cumsum: out[r,:] = cumsum(x[r,:] * mask[r,:])
// x: f32 [4096, 32768]; mask: 4-byte 0/1 words on the wire (byte fallback
// kept); out: f32 [4096, 32768].
//
// One CTA per row, 512 threads x 4 elems = 2048-elem chunks, 16 chunks/row.
// 4 CTAs/SM (launch_bounds(512,4)) -> four independent load/scan/store phase
// streams per SM to fill DRAM gaps (R3/R4 lesson: barriers & prefetch were
// not the limiter; phase overlap might be). Streaming cache hints (__ldcs /
// __stcs) since there is zero reuse.

#ifndef CUMSUM_N
#define CUMSUM_N 32768
#endif

#define TPB   512
#define VEC   4
#define CHUNK (TPB * VEC)   // 2048
#define NWARP (TPB / 32)    // 16

__global__ __launch_bounds__(TPB, 4)
void masked_cumsum_row_kernel(const float* __restrict__ x,
                              const void* __restrict__ mask,
                              float* __restrict__ out,
                              int n_cols)
{
    const int row   = blockIdx.x;
    const size_t base = (size_t)row * (size_t)n_cols;

    const int tid  = threadIdx.x;
    const int lane = tid & 31;
    const int wid  = tid >> 5;

    // --- per-warp mask dtype detection (deterministic, no barrier) ---
    // First 32 words: a 4-byte 0/1 encoding only yields 0, 1 (int32) or
    // 0x3F800000 (f32 1.0); random 0/1 BYTES produce other words w.p. 7/8.
    const unsigned probe = ((const unsigned*)mask)[lane];
    const bool clean = (probe == 0u) | (probe == 1u) | (probe == 0x3F800000u);
    const bool word_mode = __all_sync(0xffffffffu, clean);

    __shared__ float s_warp[2][NWARP];

    float carry = 0.0f;
    int p = 0;

    #pragma unroll 1
    for (int c = 0; c < n_cols; c += CHUNK) {
        const size_t off = base + (size_t)c + (size_t)tid * VEC;

        const float4 xv = __ldcs(reinterpret_cast<const float4*>(x + off));

        float v0, v1, v2, v3;
        if (word_mode) {
            const uint4 mv = __ldcs(reinterpret_cast<const uint4*>((const unsigned*)mask + off));
            v0 = mv.x ? xv.x : 0.f;
            v1 = mv.y ? xv.y : 0.f;
            v2 = mv.z ? xv.z : 0.f;
            v3 = mv.w ? xv.w : 0.f;
        } else {
            const unsigned mv = __ldcs(reinterpret_cast<const unsigned*>((const uint8_t*)mask + off));
            v0 = (mv & 0x000000FFu) ? xv.x : 0.f;
            v1 = (mv & 0x0000FF00u) ? xv.y : 0.f;
            v2 = (mv & 0x00FF0000u) ? xv.z : 0.f;
            v3 = (mv & 0xFF000000u) ? xv.w : 0.f;
        }

        // thread-local inclusive scan of 4
        const float s0 = v0;
        const float s1 = s0 + v1;
        const float s2 = s1 + v2;
        const float s3 = s2 + v3;

        // warp inclusive scan of per-thread totals
        float t = s3;
        #pragma unroll
        for (int d = 1; d < 32; d <<= 1) {
            float nv = __shfl_up_sync(0xffffffffu, t, d);
            if (lane >= d) t += nv;
        }
        const float thread_excl = t - s3;

        if (lane == 31) s_warp[p][wid] = t;
        __syncthreads();                      // the ONLY barrier per chunk

        // every warp redundantly scans the 16 warp totals
        float wincl = (lane < NWARP) ? s_warp[p][lane] : 0.f;
        #pragma unroll
        for (int d = 1; d < NWARP; d <<= 1) {
            float nv = __shfl_up_sync(0xffffffffu, wincl, d);
            if (lane >= d) wincl += nv;
        }
        const float warp_excl = (wid == 0)
            ? 0.f
            : __shfl_sync(0xffffffffu, wincl, wid - 1);
        const float block_tot = __shfl_sync(0xffffffffu, wincl, NWARP - 1);

        const float offv = carry + warp_excl + thread_excl;

        float4 o;
        o.x = s0 + offv;
        o.y = s1 + offv;
        o.z = s2 + offv;
        o.w = s3 + offv;
        __stcs(reinterpret_cast<float4*>(out + off), o);

        carry += block_tot;
        p ^= 1;    // ping-pong -> no trailing barrier needed
    }
}

extern "C" void kernel_launch(void* const* d_in, const int* in_sizes, int n_in,
                              void* d_out, int out_size)
{
    const float* x    = (const float*)d_in[0];
    const void*  mask = d_in[1];
    float*       out  = (float*)d_out;

    const int n_cols = CUMSUM_N;
    const int n_rows = in_sizes[0] / n_cols;   // 4096

    masked_cumsum_row_kernel<<<n_rows, TPB>>>(x, mask, out, n_cols);
}